// round 13
// baseline (speedup 1.0000x reference)
#include <cuda_runtime.h>
#include <cuda_bf16.h>
#include <math.h>

#define DD   512
#define SS   2048
#define BB   2
#define HH   8
#define GG   4
#define NROW (BB*SS)     // 4096
#define SR   72          // bf16 smem row stride (144B: conflict-free ldmatrix)
#define KVSZ (64*SR)     // elements per 64-row smem array (9216 B)

typedef unsigned int u32;

// ---- scratch (device globals; no allocation allowed) ----
__device__ __nv_bfloat16 g_xh[NROW*DD], g_xl[NROW*DD];
__device__ __nv_bfloat16 g_wh[6*DD*DD], g_wl[6*DD*DD];   // q1,k1,q2,k2,v,out
__device__ __nv_bfloat16 g_q1h[NROW*DD], g_q1l[NROW*DD];
__device__ __nv_bfloat16 g_q2h[NROW*DD], g_q2l[NROW*DD];
__device__ __nv_bfloat16 g_k1h[NROW*DD], g_k1l[NROW*DD];
__device__ __nv_bfloat16 g_k2h[NROW*DD], g_k2l[NROW*DD];
__device__ __nv_bfloat16 g_vth[BB*HH*64*SS], g_vtl[BB*HH*64*SS];  // [bh][hd][seq]
__device__ float g_o [NROW*DD];
__device__ __nv_bfloat16 g_oh[NROW*DD], g_ol[NROW*DD];
__device__ float g_part_s[BB*GG*32], g_part_q[BB*GG*32];
__device__ float g_mu  [BB*GG];
__device__ float g_rstd[BB*GG];

// ============================================================
// helpers
// ============================================================
__device__ __forceinline__ unsigned smem_u32(const void* p) {
    return (unsigned)__cvta_generic_to_shared(p);
}
__device__ __forceinline__ void ldsm4(u32& r0, u32& r1, u32& r2, u32& r3, unsigned a) {
    asm volatile("ldmatrix.sync.aligned.m8n8.x4.shared.b16 {%0,%1,%2,%3}, [%4];"
                 : "=r"(r0), "=r"(r1), "=r"(r2), "=r"(r3) : "r"(a));
}
__device__ __forceinline__ void mma_bf16(float* c, const u32* a, u32 b0, u32 b1) {
    asm volatile("mma.sync.aligned.m16n8k16.row.col.f32.bf16.bf16.f32 "
                 "{%0,%1,%2,%3},{%4,%5,%6,%7},{%8,%9},{%0,%1,%2,%3};"
                 : "+f"(c[0]), "+f"(c[1]), "+f"(c[2]), "+f"(c[3])
                 : "r"(a[0]), "r"(a[1]), "r"(a[2]), "r"(a[3]), "r"(b0), "r"(b1));
}
__device__ __forceinline__ void split1(float v, __nv_bfloat16& h, __nv_bfloat16& l) {
    h = __float2bfloat16(v);
    l = __float2bfloat16(v - __bfloat162float(h));
}
__device__ __forceinline__ void split2(float x, float y, u32& h, u32& l) {
    __nv_bfloat162 hh = __floats2bfloat162_rn(x, y);
    float2 hf = __bfloat1622float2(hh);
    __nv_bfloat162 ll = __floats2bfloat162_rn(x - hf.x, y - hf.y);
    h = *(u32*)&hh; l = *(u32*)&ll;
}
__device__ __forceinline__ float ex2(float x) {
    float y; asm("ex2.approx.ftz.f32 %0, %1;" : "=f"(y) : "f"(x)); return y;
}
// L1-ALLOCATING async copy (.ca): keeps cross-CTA K/V reuse in L1.
__device__ __forceinline__ void cp16(unsigned d, const void* s) {
    asm volatile("cp.async.ca.shared.global [%0], [%1], 16;" :: "r"(d), "l"(s));
}
__device__ __forceinline__ void cp_commit() {
    asm volatile("cp.async.commit_group;");
}
template<int N> __device__ __forceinline__ void cp_wait() {
    asm volatile("cp.async.wait_group %0;" :: "n"(N));
}

// ============================================================
// Kernel 0: split x and all weights into bf16 hi/lo
// (scale 0.125*log2e folded into q1w/q2w)
// ============================================================
__global__ __launch_bounds__(256) void split_inputs_kernel(
    const float* __restrict__ x,
    const float* __restrict__ q1w, const float* __restrict__ k1w,
    const float* __restrict__ q2w, const float* __restrict__ k2w,
    const float* __restrict__ vw,  const float* __restrict__ ow)
{
    const float QS = 0.125f * 1.4426950408889634f;
    const int NX = NROW*DD/4;
    const int NWEL = DD*DD/4;
    int i = blockIdx.x * 256 + threadIdx.x;
    if (i < NX) {
        float4 a = ((const float4*)x)[i];
        int e = i*4;
        split1(a.x, g_xh[e+0], g_xl[e+0]);
        split1(a.y, g_xh[e+1], g_xl[e+1]);
        split1(a.z, g_xh[e+2], g_xl[e+2]);
        split1(a.w, g_xh[e+3], g_xl[e+3]);
    } else {
        int j = i - NX;
        if (j >= 6*NWEL) return;
        int w = j / NWEL, e = j - w*NWEL;
        const float* src; float s = 1.f;
        switch (w) {
            case 0:  src = q1w; s = QS; break;
            case 1:  src = k1w; break;
            case 2:  src = q2w; s = QS; break;
            case 3:  src = k2w; break;
            case 4:  src = vw;  break;
            default: src = ow;  break;
        }
        float4 a = ((const float4*)src)[e];
        int o = w*DD*DD + e*4;
        split1(a.x*s, g_wh[o+0], g_wl[o+0]);
        split1(a.y*s, g_wh[o+1], g_wl[o+1]);
        split1(a.z*s, g_wh[o+2], g_wl[o+2]);
        split1(a.w*s, g_wh[o+3], g_wl[o+3]);
    }
}

// ============================================================
// shared bf16x3 64x64x64 tile compute (smem A)
// ============================================================
__device__ __forceinline__ void mma_tile64(
    float (*c)[4], unsigned ah_b, unsigned al_b, unsigned bh_b, unsigned bl_b,
    int arow, int acol, int browin, int bcol)
{
    #pragma unroll
    for (int ks = 0; ks < 4; ++ks) {
        unsigned aoff = (unsigned)((arow*SR + ks*16 + acol) * 2);
        u32 aH[4], aL[4];
        ldsm4(aH[0],aH[1],aH[2],aH[3], ah_b + aoff);
        ldsm4(aL[0],aL[1],aL[2],aL[3], al_b + aoff);
        #pragma unroll
        for (int np = 0; np < 4; ++np) {
            unsigned boff = (unsigned)(((np*16 + browin)*SR + ks*16 + bcol) * 2);
            u32 bH[4], bL[4];
            ldsm4(bH[0],bH[1],bH[2],bH[3], bh_b + boff);
            ldsm4(bL[0],bL[1],bL[2],bL[3], bl_b + boff);
            mma_bf16(c[2*np],   aH, bH[0], bH[1]);
            mma_bf16(c[2*np],   aH, bL[0], bL[1]);
            mma_bf16(c[2*np],   aL, bH[0], bH[1]);
            mma_bf16(c[2*np+1], aH, bH[2], bH[3]);
            mma_bf16(c[2*np+1], aH, bL[2], bL[3]);
            mma_bf16(c[2*np+1], aL, bH[2], bH[3]);
        }
    }
}

// ============================================================
// Kernel 1: fused 5-way projection GEMM (R8 synchronous version)
// grid (M/64, N/64, 5), block 128, static smem.
// ============================================================
__global__ __launch_bounds__(128) void qkv_mma_kernel(
    const float* __restrict__ k1b, const float* __restrict__ k2b)
{
    __shared__ __nv_bfloat16 Ah[64*SR], Al[64*SR], Bh[64*SR], Bl[64*SR];

    const int tid = threadIdx.x, lane = tid & 31, warp = tid >> 5;
    const int m0 = blockIdx.x * 64, n0 = blockIdx.y * 64, p = blockIdx.z;

    const __nv_bfloat16* Wh = g_wh + (size_t)p*DD*DD;
    const __nv_bfloat16* Wl = g_wl + (size_t)p*DD*DD;
    const float* bias = (p == 1) ? k1b : (p == 3) ? k2b : nullptr;

    float c[8][4] = {};

    const unsigned ah_b = smem_u32(Ah), al_b = smem_u32(Al);
    const unsigned bh_b = smem_u32(Bh), bl_b = smem_u32(Bl);
    const int arow   = warp*16 + (lane & 7) + ((lane >> 3) & 1) * 8;
    const int acol   = ((lane >> 4) << 3);
    const int browin = (lane & 7) + ((lane >> 4) << 3);
    const int bcol   = (((lane >> 3) & 1) << 3);

    for (int k0 = 0; k0 < DD; k0 += 64) {
        #pragma unroll
        for (int it = 0; it < 4; ++it) {
            int idx = tid + it*128;
            int row = idx >> 3, c8 = (idx & 7) << 3;
            size_t ga = (size_t)(m0+row)*DD + k0 + c8;
            size_t gb = (size_t)(n0+row)*DD + k0 + c8;
            *(uint4*)&Ah[row*SR+c8] = *(const uint4*)&g_xh[ga];
            *(uint4*)&Al[row*SR+c8] = *(const uint4*)&g_xl[ga];
            *(uint4*)&Bh[row*SR+c8] = *(const uint4*)&Wh[gb];
            *(uint4*)&Bl[row*SR+c8] = *(const uint4*)&Wl[gb];
        }
        __syncthreads();
        mma_tile64(c, ah_b, al_b, bh_b, bl_b, arow, acol, browin, bcol);
        __syncthreads();
    }

    const int gid = lane >> 2, tig = lane & 3;
    if (p == 4) {
        #pragma unroll
        for (int nf = 0; nf < 8; ++nf)
            #pragma unroll
            for (int e = 0; e < 4; ++e) {
                int r = m0 + warp*16 + gid + (e >> 1) * 8;
                int n = n0 + nf*8 + tig*2 + (e & 1);
                int bb = r >> 11, seq = r & 2047;
                int hh = n >> 6,  hd  = n & 63;
                size_t o = ((size_t)((bb*HH + hh)*64 + hd))*SS + seq;
                __nv_bfloat16 hi, lo; split1(c[nf][e], hi, lo);
                g_vth[o] = hi; g_vtl[o] = lo;
            }
    } else {
        __nv_bfloat16 *oh, *ol;
        switch (p) {
            case 0:  oh = g_q1h; ol = g_q1l; break;
            case 1:  oh = g_k1h; ol = g_k1l; break;
            case 2:  oh = g_q2h; ol = g_q2l; break;
            default: oh = g_k2h; ol = g_k2l; break;
        }
        #pragma unroll
        for (int nf = 0; nf < 8; ++nf)
            #pragma unroll
            for (int hf = 0; hf < 2; ++hf) {
                int r = m0 + warp*16 + gid + hf*8;
                int n = n0 + nf*8 + tig*2;
                float b0 = bias ? bias[n]   : 0.f;
                float b1 = bias ? bias[n+1] : 0.f;
                u32 h, l; split2(c[nf][2*hf] + b0, c[nf][2*hf+1] + b1, h, l);
                *(u32*)&oh[(size_t)r*DD + n] = h;
                *(u32*)&ol[(size_t)r*DD + n] = l;
            }
    }
}

// ============================================================
// Kernel 2: dual-stream flash attention (bf16x3)
// Q fragments register-resident; K/V cp.async.ca double-buffered.
// dyn smem = 2 stages x 6 arrays (k1h,k1l,k2h,k2l,vh,vl).
// ============================================================
__device__ __forceinline__ void attn_stream_tc(
    unsigned kh_b, unsigned kl_b, unsigned vh_b, unsigned vl_b,
    const u32 (*qH)[4], const u32 (*qL)[4],
    int browin, int bcol, float* m, float* l, float (*o)[4])
{
    float c[8][4] = {};
    #pragma unroll
    for (int ks = 0; ks < 4; ++ks) {
        #pragma unroll
        for (int np = 0; np < 4; ++np) {
            unsigned boff = (unsigned)(((np*16 + browin)*SR + ks*16 + bcol) * 2);
            u32 bH[4], bL[4];
            ldsm4(bH[0],bH[1],bH[2],bH[3], kh_b + boff);
            ldsm4(bL[0],bL[1],bL[2],bL[3], kl_b + boff);
            mma_bf16(c[2*np],   qH[ks], bH[0], bH[1]);
            mma_bf16(c[2*np],   qH[ks], bL[0], bL[1]);
            mma_bf16(c[2*np],   qL[ks], bH[0], bH[1]);
            mma_bf16(c[2*np+1], qH[ks], bH[2], bH[3]);
            mma_bf16(c[2*np+1], qH[ks], bL[2], bL[3]);
            mma_bf16(c[2*np+1], qL[ks], bH[2], bH[3]);
        }
    }

    #pragma unroll
    for (int hf = 0; hf < 2; ++hf) {
        float mx = -1e30f;
        #pragma unroll
        for (int nf = 0; nf < 8; ++nf)
            mx = fmaxf(mx, fmaxf(c[nf][2*hf], c[nf][2*hf+1]));
        mx = fmaxf(mx, __shfl_xor_sync(0xffffffffu, mx, 1));
        mx = fmaxf(mx, __shfl_xor_sync(0xffffffffu, mx, 2));
        float mn   = fmaxf(m[hf], mx);
        float corr = ex2(m[hf] - mn);
        float rs = 0.f;
        #pragma unroll
        for (int nf = 0; nf < 8; ++nf) {
            float p0 = ex2(c[nf][2*hf]   - mn);
            float p1 = ex2(c[nf][2*hf+1] - mn);
            c[nf][2*hf] = p0; c[nf][2*hf+1] = p1;
            rs += p0 + p1;
        }
        rs += __shfl_xor_sync(0xffffffffu, rs, 1);
        rs += __shfl_xor_sync(0xffffffffu, rs, 2);
        l[hf] = l[hf]*corr + rs;
        m[hf] = mn;
        #pragma unroll
        for (int nf = 0; nf < 8; ++nf) {
            o[nf][2*hf]   *= corr;
            o[nf][2*hf+1] *= corr;
        }
    }

    #pragma unroll
    for (int ks = 0; ks < 4; ++ks) {
        u32 pH[4], pL[4];
        split2(c[2*ks][0],   c[2*ks][1],   pH[0], pL[0]);
        split2(c[2*ks][2],   c[2*ks][3],   pH[1], pL[1]);
        split2(c[2*ks+1][0], c[2*ks+1][1], pH[2], pL[2]);
        split2(c[2*ks+1][2], c[2*ks+1][3], pH[3], pL[3]);
        #pragma unroll
        for (int np = 0; np < 4; ++np) {
            unsigned boff = (unsigned)(((np*16 + browin)*SR + ks*16 + bcol) * 2);
            u32 bH[4], bL[4];
            ldsm4(bH[0],bH[1],bH[2],bH[3], vh_b + boff);
            ldsm4(bL[0],bL[1],bL[2],bL[3], vl_b + boff);
            mma_bf16(o[2*np],   pH, bH[0], bH[1]);
            mma_bf16(o[2*np],   pH, bL[0], bL[1]);
            mma_bf16(o[2*np],   pL, bH[0], bH[1]);
            mma_bf16(o[2*np+1], pH, bH[2], bH[3]);
            mma_bf16(o[2*np+1], pH, bL[2], bL[3]);
            mma_bf16(o[2*np+1], pL, bH[2], bH[3]);
        }
    }
}

__global__ __launch_bounds__(128) void attn_mma_kernel(
    const float* __restrict__ lq1, const float* __restrict__ lk1,
    const float* __restrict__ lq2, const float* __restrict__ lk2)
{
    extern __shared__ __nv_bfloat16 sm[];
    const unsigned sbase = smem_u32(sm);
    const unsigned STGB = 6*KVSZ*2;   // stage bytes (55296)

    const int tid = threadIdx.x, lane = tid & 31, warp = tid >> 5;
    const int bh = blockIdx.y, b = bh >> 3, h = bh & 7;
    const int q0 = blockIdx.x * 64;

    const int arow   = warp*16 + (lane & 7) + ((lane >> 3) & 1) * 8;
    const int acol   = ((lane >> 4) << 3);
    const int browin = (lane & 7) + ((lane >> 4) << 3);
    const int bcol   = (((lane >> 3) & 1) << 3);

    // ---- stage Q via cp.async into stage-0 arrays 0..3, extract to regs
    {
        const size_t gq = (size_t)(b*SS + q0)*DD + h*64;
        #pragma unroll
        for (int it = 0; it < 4; ++it) {
            int idx = tid + it*128;
            int row = idx >> 3, c8 = (idx & 7) << 3;
            unsigned soff = (unsigned)((row*SR + c8) * 2);
            size_t go = gq + (size_t)row*DD + c8;
            cp16(sbase + 0*KVSZ*2 + soff, &g_q1h[go]);
            cp16(sbase + 1*KVSZ*2 + soff, &g_q1l[go]);
            cp16(sbase + 2*KVSZ*2 + soff, &g_q2h[go]);
            cp16(sbase + 3*KVSZ*2 + soff, &g_q2l[go]);
        }
        cp_commit(); cp_wait<0>(); __syncthreads();
    }
    u32 q1H[4][4], q1L[4][4], q2H[4][4], q2L[4][4];
    #pragma unroll
    for (int ks = 0; ks < 4; ++ks) {
        unsigned aoff = (unsigned)((arow*SR + ks*16 + acol) * 2);
        ldsm4(q1H[ks][0],q1H[ks][1],q1H[ks][2],q1H[ks][3], sbase + 0*KVSZ*2 + aoff);
        ldsm4(q1L[ks][0],q1L[ks][1],q1L[ks][2],q1L[ks][3], sbase + 1*KVSZ*2 + aoff);
        ldsm4(q2H[ks][0],q2H[ks][1],q2H[ks][2],q2H[ks][3], sbase + 2*KVSZ*2 + aoff);
        ldsm4(q2L[ks][0],q2L[ks][1],q2L[ks][2],q2L[ks][3], sbase + 3*KVSZ*2 + aoff);
    }
    __syncthreads();   // done reading staged Q; stage 0 reusable

    const size_t kbb = (size_t)(b*SS)*DD + h*64;
    const size_t vbb = (size_t)(bh*64)*SS;

    auto issue = [&](int t, int s) {
        unsigned st = sbase + (unsigned)s * STGB;
        size_t kb = kbb + (size_t)(t*64)*DD;
        size_t vb = vbb + t*64;
        #pragma unroll
        for (int it = 0; it < 4; ++it) {
            int idx = tid + it*128;
            int row = idx >> 3, c8 = (idx & 7) << 3;
            unsigned soff = (unsigned)((row*SR + c8) * 2);
            size_t go = kb + (size_t)row*DD + c8;
            size_t gv = vb + (size_t)row*SS + c8;
            cp16(st + 0*KVSZ*2 + soff, &g_k1h[go]);
            cp16(st + 1*KVSZ*2 + soff, &g_k1l[go]);
            cp16(st + 2*KVSZ*2 + soff, &g_k2h[go]);
            cp16(st + 3*KVSZ*2 + soff, &g_k2l[go]);
            cp16(st + 4*KVSZ*2 + soff, &g_vth[gv]);
            cp16(st + 5*KVSZ*2 + soff, &g_vtl[gv]);
        }
        cp_commit();
    };

    float o1[8][4] = {}, o2[8][4] = {};
    float m1[2] = {-1e30f, -1e30f}, l1[2] = {0.f, 0.f};
    float m2[2] = {-1e30f, -1e30f}, l2[2] = {0.f, 0.f};

    issue(0, 0);
    for (int i = 0; i < 32; ++i) {
        if (i < 31) { issue(i+1, (i+1) & 1); cp_wait<1>(); }
        else cp_wait<0>();
        __syncthreads();
        unsigned st = sbase + (unsigned)(i & 1) * STGB;
        attn_stream_tc(st + 0*KVSZ*2, st + 1*KVSZ*2, st + 4*KVSZ*2, st + 5*KVSZ*2,
                       q1H, q1L, browin, bcol, m1, l1, o1);
        attn_stream_tc(st + 2*KVSZ*2, st + 3*KVSZ*2, st + 4*KVSZ*2, st + 5*KVSZ*2,
                       q2H, q2L, browin, bcol, m2, l2, o2);
        __syncthreads();
    }

    const float lam = __expf(lq1[h]*lk1[h]) - __expf(lq2[h]*lk2[h]) + 0.2f;
    const int gid = lane >> 2, tig = lane & 3;
    const float i1[2] = {1.f/l1[0], 1.f/l1[1]};
    const float i2[2] = {lam/l2[0], lam/l2[1]};
    #pragma unroll
    for (int hf = 0; hf < 2; ++hf)
        #pragma unroll
        for (int nf = 0; nf < 8; ++nf) {
            int r = q0 + warp*16 + gid + hf*8;
            int col = h*64 + nf*8 + tig*2;
            float2 y;
            y.x = o1[nf][2*hf]  *i1[hf] - o2[nf][2*hf]  *i2[hf];
            y.y = o1[nf][2*hf+1]*i1[hf] - o2[nf][2*hf+1]*i2[hf];
            *(float2*)&g_o[(size_t)(b*SS + r)*DD + col] = y;
        }
}

// ============================================================
// Kernel 3a: GroupNorm stats stage 1 — 256 CTAs of partials
// ============================================================
__global__ __launch_bounds__(256) void gn_stats1_kernel()
{
    const int gi = blockIdx.y;
    const int b = gi >> 2, g = gi & 3;
    const int r0 = blockIdx.x * 64;
    const int tid = threadIdx.x;
    const float* base = g_o + (size_t)b*SS*DD + g*128;

    float s = 0.f, ss = 0.f;
    #pragma unroll
    for (int it = 0; it < 8; ++it) {
        int idx = tid + it*256;
        int r = idx >> 5, c4 = (idx & 31) << 2;
        float4 v = *(const float4*)&base[(size_t)(r0 + r)*DD + c4];
        s  += v.x + v.y + v.z + v.w;
        ss += v.x*v.x + v.y*v.y + v.z*v.z + v.w*v.w;
    }
    __shared__ float rs[256], rq[256];
    rs[tid] = s; rq[tid] = ss;
    __syncthreads();
    for (int off = 128; off > 0; off >>= 1) {
        if (tid < off) { rs[tid] += rs[tid+off]; rq[tid] += rq[tid+off]; }
        __syncthreads();
    }
    if (tid == 0) {
        g_part_s[gi*32 + blockIdx.x] = rs[0];
        g_part_q[gi*32 + blockIdx.x] = rq[0];
    }
}

// ============================================================
// Kernel 3b: stats stage 2
// ============================================================
__global__ __launch_bounds__(32) void gn_stats2_kernel()
{
    int gi = threadIdx.x;
    if (gi >= BB*GG) return;
    float s = 0.f, q = 0.f;
    #pragma unroll
    for (int i = 0; i < 32; ++i) {
        s += g_part_s[gi*32 + i];
        q += g_part_q[gi*32 + i];
    }
    const float n = (float)(SS*128);
    float mu  = s / n;
    float var = q / n - mu*mu;
    g_mu[gi]   = mu;
    g_rstd[gi] = rsqrtf(var + 1e-5f);
}

// ============================================================
// Kernel 3c: apply GroupNorm and split to bf16 hi/lo
// ============================================================
__global__ __launch_bounds__(256) void gn_apply_kernel(
    const float* __restrict__ gw, const float* __restrict__ gb)
{
    int i = (blockIdx.x * 256 + threadIdx.x) * 4;
    if (i >= NROW*DD) return;
    int row = i >> 9, col = i & 511;
    int gi = (row >> 11)*4 + (col >> 7);
    float mu = g_mu[gi], rst = g_rstd[gi];
    float4 a = *(const float4*)&g_o[i];
    float4 w = *(const float4*)&gw[col];
    float4 s = *(const float4*)&gb[col];
    split1((a.x - mu)*rst*w.x + s.x, g_oh[i+0], g_ol[i+0]);
    split1((a.y - mu)*rst*w.y + s.y, g_oh[i+1], g_ol[i+1]);
    split1((a.z - mu)*rst*w.z + s.z, g_oh[i+2], g_ol[i+2]);
    split1((a.w - mu)*rst*w.w + s.w, g_oh[i+3], g_ol[i+3]);
}

// ============================================================
// Kernel 4: output GEMM (R8 synchronous version)
// ============================================================
__global__ __launch_bounds__(128) void out_mma_kernel(
    const float* __restrict__ bias, float* __restrict__ y)
{
    __shared__ __nv_bfloat16 Ah[64*SR], Al[64*SR], Bh[64*SR], Bl[64*SR];

    const int tid = threadIdx.x, lane = tid & 31, warp = tid >> 5;
    const int m0 = blockIdx.x * 64, n0 = blockIdx.y * 64;

    const __nv_bfloat16* Wh = g_wh + (size_t)5*DD*DD;
    const __nv_bfloat16* Wl = g_wl + (size_t)5*DD*DD;

    float c[8][4] = {};

    const unsigned ah_b = smem_u32(Ah), al_b = smem_u32(Al);
    const unsigned bh_b = smem_u32(Bh), bl_b = smem_u32(Bl);
    const int arow   = warp*16 + (lane & 7) + ((lane >> 3) & 1) * 8;
    const int acol   = ((lane >> 4) << 3);
    const int browin = (lane & 7) + ((lane >> 4) << 3);
    const int bcol   = (((lane >> 3) & 1) << 3);

    for (int k0 = 0; k0 < DD; k0 += 64) {
        #pragma unroll
        for (int it = 0; it < 4; ++it) {
            int idx = tid + it*128;
            int row = idx >> 3, c8 = (idx & 7) << 3;
            size_t ga = (size_t)(m0+row)*DD + k0 + c8;
            size_t gb = (size_t)(n0+row)*DD + k0 + c8;
            *(uint4*)&Ah[row*SR+c8] = *(const uint4*)&g_oh[ga];
            *(uint4*)&Al[row*SR+c8] = *(const uint4*)&g_ol[ga];
            *(uint4*)&Bh[row*SR+c8] = *(const uint4*)&Wh[gb];
            *(uint4*)&Bl[row*SR+c8] = *(const uint4*)&Wl[gb];
        }
        __syncthreads();
        mma_tile64(c, ah_b, al_b, bh_b, bl_b, arow, acol, browin, bcol);
        __syncthreads();
    }

    const int gid = lane >> 2, tig = lane & 3;
    #pragma unroll
    for (int nf = 0; nf < 8; ++nf)
        #pragma unroll
        for (int hf = 0; hf < 2; ++hf) {
            int r = m0 + warp*16 + gid + hf*8;
            int n = n0 + nf*8 + tig*2;
            float2 o;
            o.x = c[nf][2*hf]   + bias[n];
            o.y = c[nf][2*hf+1] + bias[n+1];
            *(float2*)&y[(size_t)r*DD + n] = o;
        }
}

// ============================================================
// launch
// ============================================================
extern "C" void kernel_launch(void* const* d_in, const int* in_sizes, int n_in,
                              void* d_out, int out_size)
{
    const float* x   = (const float*)d_in[0];
    const float* K1w = (const float*)d_in[1];
    const float* K1b = (const float*)d_in[2];
    const float* Q1w = (const float*)d_in[3];
    const float* K2w = (const float*)d_in[4];
    const float* K2b = (const float*)d_in[5];
    const float* Q2w = (const float*)d_in[6];
    const float* Vw  = (const float*)d_in[7];
    const float* lq1 = (const float*)d_in[8];
    const float* lk1 = (const float*)d_in[9];
    const float* lq2 = (const float*)d_in[10];
    const float* lk2 = (const float*)d_in[11];
    const float* gw  = (const float*)d_in[12];
    const float* gb  = (const float*)d_in[13];
    const float* Ow  = (const float*)d_in[14];
    const float* Ob  = (const float*)d_in[15];
    float* y = (float*)d_out;

    const int ATT_SMEM = 2 * 6 * KVSZ * (int)sizeof(__nv_bfloat16);  // 110592
    cudaFuncSetAttribute(attn_mma_kernel,
                         cudaFuncAttributeMaxDynamicSharedMemorySize, ATT_SMEM);

    const int NSPLIT = (NROW*DD/4 + 6*DD*DD/4 + 255) / 256;
    split_inputs_kernel<<<NSPLIT, 256>>>(x, Q1w, K1w, Q2w, K2w, Vw, Ow);
    qkv_mma_kernel<<<dim3(NROW/64, DD/64, 5), 128>>>(K1b, K2b);
    attn_mma_kernel<<<dim3(SS/64, BB*HH), 128, ATT_SMEM>>>(lq1, lk1, lq2, lk2);
    gn_stats1_kernel<<<dim3(32, BB*GG), 256>>>();
    gn_stats2_kernel<<<1, 32>>>();
    gn_apply_kernel<<<NROW*DD/4/256, 256>>>(gw, gb);
    out_mma_kernel<<<dim3(NROW/64, DD/64), 128>>>(Ob, y);
}

// round 14
// speedup vs baseline: 1.2348x; 1.2348x over previous
#include <cuda_runtime.h>
#include <cuda_bf16.h>
#include <math.h>

#define DD   512
#define SS   2048
#define BB   2
#define HH   8
#define GG   4
#define NROW (BB*SS)     // 4096
#define SR   72          // bf16 smem row stride (144B: conflict-free ldmatrix)

typedef unsigned int u32;

// ---- scratch (device globals; no allocation allowed) ----
__device__ __nv_bfloat16 g_xh[NROW*DD], g_xl[NROW*DD];
__device__ __nv_bfloat16 g_wh[6*DD*DD], g_wl[6*DD*DD];   // q1,k1,q2,k2,v,out
__device__ __nv_bfloat16 g_q1h[NROW*DD], g_q1l[NROW*DD];
__device__ __nv_bfloat16 g_q2h[NROW*DD], g_q2l[NROW*DD];
__device__ __nv_bfloat16 g_k1h[NROW*DD], g_k1l[NROW*DD];
__device__ __nv_bfloat16 g_k2h[NROW*DD], g_k2l[NROW*DD];
__device__ __nv_bfloat16 g_vth[BB*HH*64*SS], g_vtl[BB*HH*64*SS];  // [bh][hd][seq]
__device__ float g_o1[NROW*DD], g_o2[NROW*DD];   // per-stream normalized outputs
__device__ float g_o [NROW*DD];
__device__ __nv_bfloat16 g_oh[NROW*DD], g_ol[NROW*DD];
__device__ float g_part_s[BB*GG*32], g_part_q[BB*GG*32];
__device__ float g_mu  [BB*GG];
__device__ float g_rstd[BB*GG];

// ============================================================
// helpers
// ============================================================
__device__ __forceinline__ unsigned smem_u32(const void* p) {
    return (unsigned)__cvta_generic_to_shared(p);
}
__device__ __forceinline__ void ldsm4(u32& r0, u32& r1, u32& r2, u32& r3, unsigned a) {
    asm volatile("ldmatrix.sync.aligned.m8n8.x4.shared.b16 {%0,%1,%2,%3}, [%4];"
                 : "=r"(r0), "=r"(r1), "=r"(r2), "=r"(r3) : "r"(a));
}
__device__ __forceinline__ void mma_bf16(float* c, const u32* a, u32 b0, u32 b1) {
    asm volatile("mma.sync.aligned.m16n8k16.row.col.f32.bf16.bf16.f32 "
                 "{%0,%1,%2,%3},{%4,%5,%6,%7},{%8,%9},{%0,%1,%2,%3};"
                 : "+f"(c[0]), "+f"(c[1]), "+f"(c[2]), "+f"(c[3])
                 : "r"(a[0]), "r"(a[1]), "r"(a[2]), "r"(a[3]), "r"(b0), "r"(b1));
}
__device__ __forceinline__ void split1(float v, __nv_bfloat16& h, __nv_bfloat16& l) {
    h = __float2bfloat16(v);
    l = __float2bfloat16(v - __bfloat162float(h));
}
__device__ __forceinline__ void split2(float x, float y, u32& h, u32& l) {
    __nv_bfloat162 hh = __floats2bfloat162_rn(x, y);
    float2 hf = __bfloat1622float2(hh);
    __nv_bfloat162 ll = __floats2bfloat162_rn(x - hf.x, y - hf.y);
    h = *(u32*)&hh; l = *(u32*)&ll;
}
__device__ __forceinline__ float ex2(float x) {
    float y; asm("ex2.approx.ftz.f32 %0, %1;" : "=f"(y) : "f"(x)); return y;
}

// ============================================================
// Kernel 0: split x and all weights into bf16 hi/lo
// (scale 0.125*log2e folded into q1w/q2w)
// ============================================================
__global__ __launch_bounds__(256) void split_inputs_kernel(
    const float* __restrict__ x,
    const float* __restrict__ q1w, const float* __restrict__ k1w,
    const float* __restrict__ q2w, const float* __restrict__ k2w,
    const float* __restrict__ vw,  const float* __restrict__ ow)
{
    const float QS = 0.125f * 1.4426950408889634f;
    const int NX = NROW*DD/4;
    const int NWEL = DD*DD/4;
    int i = blockIdx.x * 256 + threadIdx.x;
    if (i < NX) {
        float4 a = ((const float4*)x)[i];
        int e = i*4;
        split1(a.x, g_xh[e+0], g_xl[e+0]);
        split1(a.y, g_xh[e+1], g_xl[e+1]);
        split1(a.z, g_xh[e+2], g_xl[e+2]);
        split1(a.w, g_xh[e+3], g_xl[e+3]);
    } else {
        int j = i - NX;
        if (j >= 6*NWEL) return;
        int w = j / NWEL, e = j - w*NWEL;
        const float* src; float s = 1.f;
        switch (w) {
            case 0:  src = q1w; s = QS; break;
            case 1:  src = k1w; break;
            case 2:  src = q2w; s = QS; break;
            case 3:  src = k2w; break;
            case 4:  src = vw;  break;
            default: src = ow;  break;
        }
        float4 a = ((const float4*)src)[e];
        int o = w*DD*DD + e*4;
        split1(a.x*s, g_wh[o+0], g_wl[o+0]);
        split1(a.y*s, g_wh[o+1], g_wl[o+1]);
        split1(a.z*s, g_wh[o+2], g_wl[o+2]);
        split1(a.w*s, g_wh[o+3], g_wl[o+3]);
    }
}

// ============================================================
// shared bf16x3 64x64x64 tile compute (smem A)
// ============================================================
__device__ __forceinline__ void mma_tile64(
    float (*c)[4], unsigned ah_b, unsigned al_b, unsigned bh_b, unsigned bl_b,
    int arow, int acol, int browin, int bcol)
{
    #pragma unroll
    for (int ks = 0; ks < 4; ++ks) {
        unsigned aoff = (unsigned)((arow*SR + ks*16 + acol) * 2);
        u32 aH[4], aL[4];
        ldsm4(aH[0],aH[1],aH[2],aH[3], ah_b + aoff);
        ldsm4(aL[0],aL[1],aL[2],aL[3], al_b + aoff);
        #pragma unroll
        for (int np = 0; np < 4; ++np) {
            unsigned boff = (unsigned)(((np*16 + browin)*SR + ks*16 + bcol) * 2);
            u32 bH[4], bL[4];
            ldsm4(bH[0],bH[1],bH[2],bH[3], bh_b + boff);
            ldsm4(bL[0],bL[1],bL[2],bL[3], bl_b + boff);
            mma_bf16(c[2*np],   aH, bH[0], bH[1]);
            mma_bf16(c[2*np],   aH, bL[0], bL[1]);
            mma_bf16(c[2*np],   aL, bH[0], bH[1]);
            mma_bf16(c[2*np+1], aH, bH[2], bH[3]);
            mma_bf16(c[2*np+1], aH, bL[2], bL[3]);
            mma_bf16(c[2*np+1], aL, bH[2], bH[3]);
        }
    }
}

// ============================================================
// Kernel 1: fused 5-way projection GEMM (R8 synchronous version)
// ============================================================
__global__ __launch_bounds__(128) void qkv_mma_kernel(
    const float* __restrict__ k1b, const float* __restrict__ k2b)
{
    __shared__ __nv_bfloat16 Ah[64*SR], Al[64*SR], Bh[64*SR], Bl[64*SR];

    const int tid = threadIdx.x, lane = tid & 31, warp = tid >> 5;
    const int m0 = blockIdx.x * 64, n0 = blockIdx.y * 64, p = blockIdx.z;

    const __nv_bfloat16* Wh = g_wh + (size_t)p*DD*DD;
    const __nv_bfloat16* Wl = g_wl + (size_t)p*DD*DD;
    const float* bias = (p == 1) ? k1b : (p == 3) ? k2b : nullptr;

    float c[8][4] = {};

    const unsigned ah_b = smem_u32(Ah), al_b = smem_u32(Al);
    const unsigned bh_b = smem_u32(Bh), bl_b = smem_u32(Bl);
    const int arow   = warp*16 + (lane & 7) + ((lane >> 3) & 1) * 8;
    const int acol   = ((lane >> 4) << 3);
    const int browin = (lane & 7) + ((lane >> 4) << 3);
    const int bcol   = (((lane >> 3) & 1) << 3);

    for (int k0 = 0; k0 < DD; k0 += 64) {
        #pragma unroll
        for (int it = 0; it < 4; ++it) {
            int idx = tid + it*128;
            int row = idx >> 3, c8 = (idx & 7) << 3;
            size_t ga = (size_t)(m0+row)*DD + k0 + c8;
            size_t gb = (size_t)(n0+row)*DD + k0 + c8;
            *(uint4*)&Ah[row*SR+c8] = *(const uint4*)&g_xh[ga];
            *(uint4*)&Al[row*SR+c8] = *(const uint4*)&g_xl[ga];
            *(uint4*)&Bh[row*SR+c8] = *(const uint4*)&Wh[gb];
            *(uint4*)&Bl[row*SR+c8] = *(const uint4*)&Wl[gb];
        }
        __syncthreads();
        mma_tile64(c, ah_b, al_b, bh_b, bl_b, arow, acol, browin, bcol);
        __syncthreads();
    }

    const int gid = lane >> 2, tig = lane & 3;
    if (p == 4) {
        #pragma unroll
        for (int nf = 0; nf < 8; ++nf)
            #pragma unroll
            for (int e = 0; e < 4; ++e) {
                int r = m0 + warp*16 + gid + (e >> 1) * 8;
                int n = n0 + nf*8 + tig*2 + (e & 1);
                int bb = r >> 11, seq = r & 2047;
                int hh = n >> 6,  hd  = n & 63;
                size_t o = ((size_t)((bb*HH + hh)*64 + hd))*SS + seq;
                __nv_bfloat16 hi, lo; split1(c[nf][e], hi, lo);
                g_vth[o] = hi; g_vtl[o] = lo;
            }
    } else {
        __nv_bfloat16 *oh, *ol;
        switch (p) {
            case 0:  oh = g_q1h; ol = g_q1l; break;
            case 1:  oh = g_k1h; ol = g_k1l; break;
            case 2:  oh = g_q2h; ol = g_q2l; break;
            default: oh = g_k2h; ol = g_k2l; break;
        }
        #pragma unroll
        for (int nf = 0; nf < 8; ++nf)
            #pragma unroll
            for (int hf = 0; hf < 2; ++hf) {
                int r = m0 + warp*16 + gid + hf*8;
                int n = n0 + nf*8 + tig*2;
                float b0 = bias ? bias[n]   : 0.f;
                float b1 = bias ? bias[n+1] : 0.f;
                u32 h, l; split2(c[nf][2*hf] + b0, c[nf][2*hf+1] + b1, h, l);
                *(u32*)&oh[(size_t)r*DD + n] = h;
                *(u32*)&ol[(size_t)r*DD + n] = l;
            }
    }
}

// ============================================================
// Kernel 2: PER-STREAM flash attention (bf16x3)
// grid (S/64, B*H, 2) — blockIdx.z selects softmax stream.
// Q register-resident; K/V in 4 smem arrays (37 KB) -> 3 CTAs/SM.
// Writes o_s/l_s (normalized) to g_o1/g_o2; combine kernel applies λ.
// ============================================================
__global__ __launch_bounds__(128) void attn_mma_kernel()
{
    __shared__ __nv_bfloat16 Kh[64*SR], Kl[64*SR], Vh[64*SR], Vl[64*SR];

    const int tid = threadIdx.x, lane = tid & 31, warp = tid >> 5;
    const int bh = blockIdx.y, b = bh >> 3;
    const int q0 = blockIdx.x * 64;
    const int stream = blockIdx.z;

    const __nv_bfloat16 *qh_g, *ql_g, *kh_g, *kl_g; float* og;
    if (stream == 0) { qh_g = g_q1h; ql_g = g_q1l; kh_g = g_k1h; kl_g = g_k1l; og = g_o1; }
    else             { qh_g = g_q2h; ql_g = g_q2l; kh_g = g_k2h; kl_g = g_k2l; og = g_o2; }

    const unsigned kh_b = smem_u32(Kh), kl_b = smem_u32(Kl);
    const unsigned vh_b = smem_u32(Vh), vl_b = smem_u32(Vl);

    const int arow   = warp*16 + (lane & 7) + ((lane >> 3) & 1) * 8;
    const int acol   = ((lane >> 4) << 3);
    const int browin = (lane & 7) + ((lane >> 4) << 3);
    const int bcol   = (((lane >> 3) & 1) << 3);
    const int h = bh & 7;

    // ---- stage Q through Kh/Kl smem, extract fragments to registers
    {
        const size_t gq = (size_t)(b*SS + q0)*DD + h*64;
        #pragma unroll
        for (int it = 0; it < 4; ++it) {
            int idx = tid + it*128;
            int row = idx >> 3, c8 = (idx & 7) << 3;
            size_t go = gq + (size_t)row*DD + c8;
            *(uint4*)&Kh[row*SR+c8] = *(const uint4*)&qh_g[go];
            *(uint4*)&Kl[row*SR+c8] = *(const uint4*)&ql_g[go];
        }
        __syncthreads();
    }
    u32 qH[4][4], qL[4][4];
    #pragma unroll
    for (int ks = 0; ks < 4; ++ks) {
        unsigned aoff = (unsigned)((arow*SR + ks*16 + acol) * 2);
        ldsm4(qH[ks][0],qH[ks][1],qH[ks][2],qH[ks][3], kh_b + aoff);
        ldsm4(qL[ks][0],qL[ks][1],qL[ks][2],qL[ks][3], kl_b + aoff);
    }
    __syncthreads();

    float o[8][4] = {};
    float m[2] = {-1e30f, -1e30f}, l[2] = {0.f, 0.f};

    const size_t kbb = (size_t)(b*SS)*DD + h*64;
    const size_t vbb = (size_t)(bh*64)*SS;

    for (int kc = 0; kc < SS; kc += 64) {
        const size_t kb = kbb + (size_t)kc*DD;
        const size_t vb = vbb + kc;
        #pragma unroll
        for (int it = 0; it < 4; ++it) {
            int idx = tid + it*128;
            int row = idx >> 3, c8 = (idx & 7) << 3;
            size_t go = kb + (size_t)row*DD + c8;
            size_t gv = vb + (size_t)row*SS + c8;
            *(uint4*)&Kh[row*SR+c8] = *(const uint4*)&kh_g[go];
            *(uint4*)&Kl[row*SR+c8] = *(const uint4*)&kl_g[go];
            *(uint4*)&Vh[row*SR+c8] = *(const uint4*)&g_vth[gv];
            *(uint4*)&Vl[row*SR+c8] = *(const uint4*)&g_vtl[gv];
        }
        __syncthreads();

        // S = q @ k^T (scale folded into q weights; base-2 softmax)
        float c[8][4] = {};
        #pragma unroll
        for (int ks = 0; ks < 4; ++ks) {
            #pragma unroll
            for (int np = 0; np < 4; ++np) {
                unsigned boff = (unsigned)(((np*16 + browin)*SR + ks*16 + bcol) * 2);
                u32 bH[4], bL[4];
                ldsm4(bH[0],bH[1],bH[2],bH[3], kh_b + boff);
                ldsm4(bL[0],bL[1],bL[2],bL[3], kl_b + boff);
                mma_bf16(c[2*np],   qH[ks], bH[0], bH[1]);
                mma_bf16(c[2*np],   qH[ks], bL[0], bL[1]);
                mma_bf16(c[2*np],   qL[ks], bH[0], bH[1]);
                mma_bf16(c[2*np+1], qH[ks], bH[2], bH[3]);
                mma_bf16(c[2*np+1], qH[ks], bL[2], bL[3]);
                mma_bf16(c[2*np+1], qL[ks], bH[2], bH[3]);
            }
        }

        // online softmax
        #pragma unroll
        for (int hf = 0; hf < 2; ++hf) {
            float mx = -1e30f;
            #pragma unroll
            for (int nf = 0; nf < 8; ++nf)
                mx = fmaxf(mx, fmaxf(c[nf][2*hf], c[nf][2*hf+1]));
            mx = fmaxf(mx, __shfl_xor_sync(0xffffffffu, mx, 1));
            mx = fmaxf(mx, __shfl_xor_sync(0xffffffffu, mx, 2));
            float mn   = fmaxf(m[hf], mx);
            float corr = ex2(m[hf] - mn);
            float rs = 0.f;
            #pragma unroll
            for (int nf = 0; nf < 8; ++nf) {
                float p0 = ex2(c[nf][2*hf]   - mn);
                float p1 = ex2(c[nf][2*hf+1] - mn);
                c[nf][2*hf] = p0; c[nf][2*hf+1] = p1;
                rs += p0 + p1;
            }
            rs += __shfl_xor_sync(0xffffffffu, rs, 1);
            rs += __shfl_xor_sync(0xffffffffu, rs, 2);
            l[hf] = l[hf]*corr + rs;
            m[hf] = mn;
            #pragma unroll
            for (int nf = 0; nf < 8; ++nf) {
                o[nf][2*hf]   *= corr;
                o[nf][2*hf+1] *= corr;
            }
        }

        // O += P @ V
        #pragma unroll
        for (int ks = 0; ks < 4; ++ks) {
            u32 pH[4], pL[4];
            split2(c[2*ks][0],   c[2*ks][1],   pH[0], pL[0]);
            split2(c[2*ks][2],   c[2*ks][3],   pH[1], pL[1]);
            split2(c[2*ks+1][0], c[2*ks+1][1], pH[2], pL[2]);
            split2(c[2*ks+1][2], c[2*ks+1][3], pH[3], pL[3]);
            #pragma unroll
            for (int np = 0; np < 4; ++np) {
                unsigned boff = (unsigned)(((np*16 + browin)*SR + ks*16 + bcol) * 2);
                u32 bH[4], bL[4];
                ldsm4(bH[0],bH[1],bH[2],bH[3], vh_b + boff);
                ldsm4(bL[0],bL[1],bL[2],bL[3], vl_b + boff);
                mma_bf16(o[2*np],   pH, bH[0], bH[1]);
                mma_bf16(o[2*np],   pH, bL[0], bL[1]);
                mma_bf16(o[2*np],   pL, bH[0], bH[1]);
                mma_bf16(o[2*np+1], pH, bH[2], bH[3]);
                mma_bf16(o[2*np+1], pH, bL[2], bL[3]);
                mma_bf16(o[2*np+1], pL, bH[2], bH[3]);
            }
        }
        __syncthreads();
    }

    const int gid = lane >> 2, tig = lane & 3;
    const float inv[2] = {1.f/l[0], 1.f/l[1]};
    #pragma unroll
    for (int hf = 0; hf < 2; ++hf)
        #pragma unroll
        for (int nf = 0; nf < 8; ++nf) {
            int r = q0 + warp*16 + gid + hf*8;
            int col = h*64 + nf*8 + tig*2;
            float2 y;
            y.x = o[nf][2*hf]  *inv[hf];
            y.y = o[nf][2*hf+1]*inv[hf];
            *(float2*)&og[(size_t)(b*SS + r)*DD + col] = y;
        }
}

// ============================================================
// Kernel 2b: combine streams  g_o = o1 - lam[h]*o2
// ============================================================
__global__ __launch_bounds__(256) void combine_kernel(
    const float* __restrict__ lq1, const float* __restrict__ lk1,
    const float* __restrict__ lq2, const float* __restrict__ lk2)
{
    int i = (blockIdx.x * 256 + threadIdx.x) * 4;
    if (i >= NROW*DD) return;
    int h = (i & 511) >> 6;          // 4-aligned, same head for all 4 lanes
    float lam = __expf(lq1[h]*lk1[h]) - __expf(lq2[h]*lk2[h]) + 0.2f;
    float4 a = *(const float4*)&g_o1[i];
    float4 c = *(const float4*)&g_o2[i];
    float4 r;
    r.x = a.x - lam*c.x; r.y = a.y - lam*c.y;
    r.z = a.z - lam*c.z; r.w = a.w - lam*c.w;
    *(float4*)&g_o[i] = r;
}

// ============================================================
// Kernel 3a: GroupNorm stats stage 1 — 256 CTAs of partials
// ============================================================
__global__ __launch_bounds__(256) void gn_stats1_kernel()
{
    const int gi = blockIdx.y;
    const int b = gi >> 2, g = gi & 3;
    const int r0 = blockIdx.x * 64;
    const int tid = threadIdx.x;
    const float* base = g_o + (size_t)b*SS*DD + g*128;

    float s = 0.f, ss = 0.f;
    #pragma unroll
    for (int it = 0; it < 8; ++it) {
        int idx = tid + it*256;
        int r = idx >> 5, c4 = (idx & 31) << 2;
        float4 v = *(const float4*)&base[(size_t)(r0 + r)*DD + c4];
        s  += v.x + v.y + v.z + v.w;
        ss += v.x*v.x + v.y*v.y + v.z*v.z + v.w*v.w;
    }
    __shared__ float rs[256], rq[256];
    rs[tid] = s; rq[tid] = ss;
    __syncthreads();
    for (int off = 128; off > 0; off >>= 1) {
        if (tid < off) { rs[tid] += rs[tid+off]; rq[tid] += rq[tid+off]; }
        __syncthreads();
    }
    if (tid == 0) {
        g_part_s[gi*32 + blockIdx.x] = rs[0];
        g_part_q[gi*32 + blockIdx.x] = rq[0];
    }
}

// ============================================================
// Kernel 3b: stats stage 2
// ============================================================
__global__ __launch_bounds__(32) void gn_stats2_kernel()
{
    int gi = threadIdx.x;
    if (gi >= BB*GG) return;
    float s = 0.f, q = 0.f;
    #pragma unroll
    for (int i = 0; i < 32; ++i) {
        s += g_part_s[gi*32 + i];
        q += g_part_q[gi*32 + i];
    }
    const float n = (float)(SS*128);
    float mu  = s / n;
    float var = q / n - mu*mu;
    g_mu[gi]   = mu;
    g_rstd[gi] = rsqrtf(var + 1e-5f);
}

// ============================================================
// Kernel 3c: apply GroupNorm and split to bf16 hi/lo
// ============================================================
__global__ __launch_bounds__(256) void gn_apply_kernel(
    const float* __restrict__ gw, const float* __restrict__ gb)
{
    int i = (blockIdx.x * 256 + threadIdx.x) * 4;
    if (i >= NROW*DD) return;
    int row = i >> 9, col = i & 511;
    int gi = (row >> 11)*4 + (col >> 7);
    float mu = g_mu[gi], rst = g_rstd[gi];
    float4 a = *(const float4*)&g_o[i];
    float4 w = *(const float4*)&gw[col];
    float4 s = *(const float4*)&gb[col];
    split1((a.x - mu)*rst*w.x + s.x, g_oh[i+0], g_ol[i+0]);
    split1((a.y - mu)*rst*w.y + s.y, g_oh[i+1], g_ol[i+1]);
    split1((a.z - mu)*rst*w.z + s.z, g_oh[i+2], g_ol[i+2]);
    split1((a.w - mu)*rst*w.w + s.w, g_oh[i+3], g_ol[i+3]);
}

// ============================================================
// Kernel 4: output GEMM (R8 synchronous version)
// ============================================================
__global__ __launch_bounds__(128) void out_mma_kernel(
    const float* __restrict__ bias, float* __restrict__ y)
{
    __shared__ __nv_bfloat16 Ah[64*SR], Al[64*SR], Bh[64*SR], Bl[64*SR];

    const int tid = threadIdx.x, lane = tid & 31, warp = tid >> 5;
    const int m0 = blockIdx.x * 64, n0 = blockIdx.y * 64;

    const __nv_bfloat16* Wh = g_wh + (size_t)5*DD*DD;
    const __nv_bfloat16* Wl = g_wl + (size_t)5*DD*DD;

    float c[8][4] = {};

    const unsigned ah_b = smem_u32(Ah), al_b = smem_u32(Al);
    const unsigned bh_b = smem_u32(Bh), bl_b = smem_u32(Bl);
    const int arow   = warp*16 + (lane & 7) + ((lane >> 3) & 1) * 8;
    const int acol   = ((lane >> 4) << 3);
    const int browin = (lane & 7) + ((lane >> 4) << 3);
    const int bcol   = (((lane >> 3) & 1) << 3);

    for (int k0 = 0; k0 < DD; k0 += 64) {
        #pragma unroll
        for (int it = 0; it < 4; ++it) {
            int idx = tid + it*128;
            int row = idx >> 3, c8 = (idx & 7) << 3;
            size_t ga = (size_t)(m0+row)*DD + k0 + c8;
            size_t gb = (size_t)(n0+row)*DD + k0 + c8;
            *(uint4*)&Ah[row*SR+c8] = *(const uint4*)&g_oh[ga];
            *(uint4*)&Al[row*SR+c8] = *(const uint4*)&g_ol[ga];
            *(uint4*)&Bh[row*SR+c8] = *(const uint4*)&Wh[gb];
            *(uint4*)&Bl[row*SR+c8] = *(const uint4*)&Wl[gb];
        }
        __syncthreads();
        mma_tile64(c, ah_b, al_b, bh_b, bl_b, arow, acol, browin, bcol);
        __syncthreads();
    }

    const int gid = lane >> 2, tig = lane & 3;
    #pragma unroll
    for (int nf = 0; nf < 8; ++nf)
        #pragma unroll
        for (int hf = 0; hf < 2; ++hf) {
            int r = m0 + warp*16 + gid + hf*8;
            int n = n0 + nf*8 + tig*2;
            float2 o;
            o.x = c[nf][2*hf]   + bias[n];
            o.y = c[nf][2*hf+1] + bias[n+1];
            *(float2*)&y[(size_t)r*DD + n] = o;
        }
}

// ============================================================
// launch
// ============================================================
extern "C" void kernel_launch(void* const* d_in, const int* in_sizes, int n_in,
                              void* d_out, int out_size)
{
    const float* x   = (const float*)d_in[0];
    const float* K1w = (const float*)d_in[1];
    const float* K1b = (const float*)d_in[2];
    const float* Q1w = (const float*)d_in[3];
    const float* K2w = (const float*)d_in[4];
    const float* K2b = (const float*)d_in[5];
    const float* Q2w = (const float*)d_in[6];
    const float* Vw  = (const float*)d_in[7];
    const float* lq1 = (const float*)d_in[8];
    const float* lk1 = (const float*)d_in[9];
    const float* lq2 = (const float*)d_in[10];
    const float* lk2 = (const float*)d_in[11];
    const float* gw  = (const float*)d_in[12];
    const float* gb  = (const float*)d_in[13];
    const float* Ow  = (const float*)d_in[14];
    const float* Ob  = (const float*)d_in[15];
    float* y = (float*)d_out;

    const int NSPLIT = (NROW*DD/4 + 6*DD*DD/4 + 255) / 256;
    split_inputs_kernel<<<NSPLIT, 256>>>(x, Q1w, K1w, Q2w, K2w, Vw, Ow);
    qkv_mma_kernel<<<dim3(NROW/64, DD/64, 5), 128>>>(K1b, K2b);
    attn_mma_kernel<<<dim3(SS/64, BB*HH, 2), 128>>>();
    combine_kernel<<<NROW*DD/4/256, 256>>>(lq1, lk1, lq2, lk2);
    gn_stats1_kernel<<<dim3(32, BB*GG), 256>>>();
    gn_stats2_kernel<<<1, 32>>>();
    gn_apply_kernel<<<NROW*DD/4/256, 256>>>(gw, gb);
    out_mma_kernel<<<dim3(NROW/64, DD/64), 128>>>(Ob, y);
}

// round 17
// speedup vs baseline: 1.2450x; 1.0083x over previous
#include <cuda_runtime.h>
#include <cuda_bf16.h>
#include <math.h>

#define DD   512
#define SS   2048
#define BB   2
#define HH   8
#define GG   4
#define NROW (BB*SS)     // 4096
#define SR   72          // bf16 smem row stride (144B: conflict-free ldmatrix)

typedef unsigned int u32;

// ---- scratch (device globals; no allocation allowed) ----
__device__ __nv_bfloat16 g_xh[NROW*DD], g_xl[NROW*DD];
__device__ __nv_bfloat16 g_wh[6*DD*DD], g_wl[6*DD*DD];   // q1,k1,q2,k2,v,out
__device__ __nv_bfloat16 g_q1h[NROW*DD], g_q1l[NROW*DD];
__device__ __nv_bfloat16 g_q2h[NROW*DD], g_q2l[NROW*DD];
__device__ __nv_bfloat16 g_k1h[NROW*DD], g_k1l[NROW*DD];
__device__ __nv_bfloat16 g_k2h[NROW*DD], g_k2l[NROW*DD];
__device__ __nv_bfloat16 g_vth[BB*HH*64*SS], g_vtl[BB*HH*64*SS];  // [bh][hd][seq]
__device__ float g_o1[NROW*DD], g_o2[NROW*DD];   // per-stream normalized outputs
__device__ float g_o [NROW*DD];
__device__ float g_part_s[BB*GG*32], g_part_q[BB*GG*32];
__device__ float g_mu  [BB*GG];
__device__ float g_rstd[BB*GG];

// ============================================================
// helpers
// ============================================================
__device__ __forceinline__ unsigned smem_u32(const void* p) {
    return (unsigned)__cvta_generic_to_shared(p);
}
__device__ __forceinline__ void ldsm4(u32& r0, u32& r1, u32& r2, u32& r3, unsigned a) {
    asm volatile("ldmatrix.sync.aligned.m8n8.x4.shared.b16 {%0,%1,%2,%3}, [%4];"
                 : "=r"(r0), "=r"(r1), "=r"(r2), "=r"(r3) : "r"(a));
}
__device__ __forceinline__ void mma_bf16(float* c, const u32* a, u32 b0, u32 b1) {
    asm volatile("mma.sync.aligned.m16n8k16.row.col.f32.bf16.bf16.f32 "
                 "{%0,%1,%2,%3},{%4,%5,%6,%7},{%8,%9},{%0,%1,%2,%3};"
                 : "+f"(c[0]), "+f"(c[1]), "+f"(c[2]), "+f"(c[3])
                 : "r"(a[0]), "r"(a[1]), "r"(a[2]), "r"(a[3]), "r"(b0), "r"(b1));
}
__device__ __forceinline__ void split1(float v, __nv_bfloat16& h, __nv_bfloat16& l) {
    h = __float2bfloat16(v);
    l = __float2bfloat16(v - __bfloat162float(h));
}
__device__ __forceinline__ void split2(float x, float y, u32& h, u32& l) {
    __nv_bfloat162 hh = __floats2bfloat162_rn(x, y);
    float2 hf = __bfloat1622float2(hh);
    __nv_bfloat162 ll = __floats2bfloat162_rn(x - hf.x, y - hf.y);
    h = *(u32*)&hh; l = *(u32*)&ll;
}
__device__ __forceinline__ float ex2(float x) {
    float y; asm("ex2.approx.ftz.f32 %0, %1;" : "=f"(y) : "f"(x)); return y;
}

// ============================================================
// Kernel 0: split x and all weights into bf16 hi/lo
// ============================================================
__global__ __launch_bounds__(256) void split_inputs_kernel(
    const float* __restrict__ x,
    const float* __restrict__ q1w, const float* __restrict__ k1w,
    const float* __restrict__ q2w, const float* __restrict__ k2w,
    const float* __restrict__ vw,  const float* __restrict__ ow)
{
    const float QS = 0.125f * 1.4426950408889634f;
    const int NX = NROW*DD/4;
    const int NWEL = DD*DD/4;
    int i = blockIdx.x * 256 + threadIdx.x;
    if (i < NX) {
        float4 a = ((const float4*)x)[i];
        int e = i*4;
        split1(a.x, g_xh[e+0], g_xl[e+0]);
        split1(a.y, g_xh[e+1], g_xl[e+1]);
        split1(a.z, g_xh[e+2], g_xl[e+2]);
        split1(a.w, g_xh[e+3], g_xl[e+3]);
    } else {
        int j = i - NX;
        if (j >= 6*NWEL) return;
        int w = j / NWEL, e = j - w*NWEL;
        const float* src; float s = 1.f;
        switch (w) {
            case 0:  src = q1w; s = QS; break;
            case 1:  src = k1w; break;
            case 2:  src = q2w; s = QS; break;
            case 3:  src = k2w; break;
            case 4:  src = vw;  break;
            default: src = ow;  break;
        }
        float4 a = ((const float4*)src)[e];
        int o = w*DD*DD + e*4;
        split1(a.x*s, g_wh[o+0], g_wl[o+0]);
        split1(a.y*s, g_wh[o+1], g_wl[o+1]);
        split1(a.z*s, g_wh[o+2], g_wl[o+2]);
        split1(a.w*s, g_wh[o+3], g_wl[o+3]);
    }
}

// ============================================================
// shared bf16x3 64x64x64 tile compute
// ============================================================
__device__ __forceinline__ void mma_tile64(
    float (*c)[4], unsigned ah_b, unsigned al_b, unsigned bh_b, unsigned bl_b,
    int arow, int acol, int browin, int bcol)
{
    #pragma unroll
    for (int ks = 0; ks < 4; ++ks) {
        unsigned aoff = (unsigned)((arow*SR + ks*16 + acol) * 2);
        u32 aH[4], aL[4];
        ldsm4(aH[0],aH[1],aH[2],aH[3], ah_b + aoff);
        ldsm4(aL[0],aL[1],aL[2],aL[3], al_b + aoff);
        #pragma unroll
        for (int np = 0; np < 4; ++np) {
            unsigned boff = (unsigned)(((np*16 + browin)*SR + ks*16 + bcol) * 2);
            u32 bH[4], bL[4];
            ldsm4(bH[0],bH[1],bH[2],bH[3], bh_b + boff);
            ldsm4(bL[0],bL[1],bL[2],bL[3], bl_b + boff);
            mma_bf16(c[2*np],   aH, bH[0], bH[1]);
            mma_bf16(c[2*np],   aH, bL[0], bL[1]);
            mma_bf16(c[2*np],   aL, bH[0], bH[1]);
            mma_bf16(c[2*np+1], aH, bH[2], bH[3]);
            mma_bf16(c[2*np+1], aH, bL[2], bL[3]);
            mma_bf16(c[2*np+1], aL, bH[2], bH[3]);
        }
    }
}

// ============================================================
// Kernel 1: fused 5-way projection GEMM (synchronous)
// ============================================================
__global__ __launch_bounds__(128) void qkv_mma_kernel(
    const float* __restrict__ k1b, const float* __restrict__ k2b)
{
    __shared__ __nv_bfloat16 Ah[64*SR], Al[64*SR], Bh[64*SR], Bl[64*SR];

    const int tid = threadIdx.x, lane = tid & 31, warp = tid >> 5;
    const int m0 = blockIdx.x * 64, n0 = blockIdx.y * 64, p = blockIdx.z;

    const __nv_bfloat16* Wh = g_wh + (size_t)p*DD*DD;
    const __nv_bfloat16* Wl = g_wl + (size_t)p*DD*DD;
    const float* bias = (p == 1) ? k1b : (p == 3) ? k2b : nullptr;

    float c[8][4] = {};

    const unsigned ah_b = smem_u32(Ah), al_b = smem_u32(Al);
    const unsigned bh_b = smem_u32(Bh), bl_b = smem_u32(Bl);
    const int arow   = warp*16 + (lane & 7) + ((lane >> 3) & 1) * 8;
    const int acol   = ((lane >> 4) << 3);
    const int browin = (lane & 7) + ((lane >> 4) << 3);
    const int bcol   = (((lane >> 3) & 1) << 3);

    for (int k0 = 0; k0 < DD; k0 += 64) {
        #pragma unroll
        for (int it = 0; it < 4; ++it) {
            int idx = tid + it*128;
            int row = idx >> 3, c8 = (idx & 7) << 3;
            size_t ga = (size_t)(m0+row)*DD + k0 + c8;
            size_t gb = (size_t)(n0+row)*DD + k0 + c8;
            *(uint4*)&Ah[row*SR+c8] = *(const uint4*)&g_xh[ga];
            *(uint4*)&Al[row*SR+c8] = *(const uint4*)&g_xl[ga];
            *(uint4*)&Bh[row*SR+c8] = *(const uint4*)&Wh[gb];
            *(uint4*)&Bl[row*SR+c8] = *(const uint4*)&Wl[gb];
        }
        __syncthreads();
        mma_tile64(c, ah_b, al_b, bh_b, bl_b, arow, acol, browin, bcol);
        __syncthreads();
    }

    const int gid = lane >> 2, tig = lane & 3;
    if (p == 4) {
        #pragma unroll
        for (int nf = 0; nf < 8; ++nf)
            #pragma unroll
            for (int e = 0; e < 4; ++e) {
                int r = m0 + warp*16 + gid + (e >> 1) * 8;
                int n = n0 + nf*8 + tig*2 + (e & 1);
                int bb = r >> 11, seq = r & 2047;
                int hh = n >> 6,  hd  = n & 63;
                size_t o = ((size_t)((bb*HH + hh)*64 + hd))*SS + seq;
                __nv_bfloat16 hi, lo; split1(c[nf][e], hi, lo);
                g_vth[o] = hi; g_vtl[o] = lo;
            }
    } else {
        __nv_bfloat16 *oh, *ol;
        switch (p) {
            case 0:  oh = g_q1h; ol = g_q1l; break;
            case 1:  oh = g_k1h; ol = g_k1l; break;
            case 2:  oh = g_q2h; ol = g_q2l; break;
            default: oh = g_k2h; ol = g_k2l; break;
        }
        #pragma unroll
        for (int nf = 0; nf < 8; ++nf)
            #pragma unroll
            for (int hf = 0; hf < 2; ++hf) {
                int r = m0 + warp*16 + gid + hf*8;
                int n = n0 + nf*8 + tig*2;
                float b0 = bias ? bias[n]   : 0.f;
                float b1 = bias ? bias[n+1] : 0.f;
                u32 h, l; split2(c[nf][2*hf] + b0, c[nf][2*hf+1] + b1, h, l);
                *(u32*)&oh[(size_t)r*DD + n] = h;
                *(u32*)&ol[(size_t)r*DD + n] = l;
            }
    }
}

// ============================================================
// Kernel 2: PER-STREAM flash attention (bf16x3), >=3 CTAs/SM
// ============================================================
__global__ __launch_bounds__(128, 3) void attn_mma_kernel()
{
    __shared__ __nv_bfloat16 Kh[64*SR], Kl[64*SR], Vh[64*SR], Vl[64*SR];

    const int tid = threadIdx.x, lane = tid & 31, warp = tid >> 5;
    const int bh = blockIdx.y, b = bh >> 3;
    const int q0 = blockIdx.x * 64;
    const int stream = blockIdx.z;

    const __nv_bfloat16 *qh_g, *ql_g, *kh_g, *kl_g; float* og;
    if (stream == 0) { qh_g = g_q1h; ql_g = g_q1l; kh_g = g_k1h; kl_g = g_k1l; og = g_o1; }
    else             { qh_g = g_q2h; ql_g = g_q2l; kh_g = g_k2h; kl_g = g_k2l; og = g_o2; }

    const unsigned kh_b = smem_u32(Kh), kl_b = smem_u32(Kl);
    const unsigned vh_b = smem_u32(Vh), vl_b = smem_u32(Vl);

    const int arow   = warp*16 + (lane & 7) + ((lane >> 3) & 1) * 8;
    const int acol   = ((lane >> 4) << 3);
    const int browin = (lane & 7) + ((lane >> 4) << 3);
    const int bcol   = (((lane >> 3) & 1) << 3);
    const int h = bh & 7;

    {
        const size_t gq = (size_t)(b*SS + q0)*DD + h*64;
        #pragma unroll
        for (int it = 0; it < 4; ++it) {
            int idx = tid + it*128;
            int row = idx >> 3, c8 = (idx & 7) << 3;
            size_t go = gq + (size_t)row*DD + c8;
            *(uint4*)&Kh[row*SR+c8] = *(const uint4*)&qh_g[go];
            *(uint4*)&Kl[row*SR+c8] = *(const uint4*)&ql_g[go];
        }
        __syncthreads();
    }
    u32 qH[4][4], qL[4][4];
    #pragma unroll
    for (int ks = 0; ks < 4; ++ks) {
        unsigned aoff = (unsigned)((arow*SR + ks*16 + acol) * 2);
        ldsm4(qH[ks][0],qH[ks][1],qH[ks][2],qH[ks][3], kh_b + aoff);
        ldsm4(qL[ks][0],qL[ks][1],qL[ks][2],qL[ks][3], kl_b + aoff);
    }
    __syncthreads();

    float o[8][4] = {};
    float m[2] = {-1e30f, -1e30f}, l[2] = {0.f, 0.f};

    const size_t kbb = (size_t)(b*SS)*DD + h*64;
    const size_t vbb = (size_t)(bh*64)*SS;

    for (int kc = 0; kc < SS; kc += 64) {
        const size_t kb = kbb + (size_t)kc*DD;
        const size_t vb = vbb + kc;
        #pragma unroll
        for (int it = 0; it < 4; ++it) {
            int idx = tid + it*128;
            int row = idx >> 3, c8 = (idx & 7) << 3;
            size_t go = kb + (size_t)row*DD + c8;
            size_t gv = vb + (size_t)row*SS + c8;
            *(uint4*)&Kh[row*SR+c8] = *(const uint4*)&kh_g[go];
            *(uint4*)&Kl[row*SR+c8] = *(const uint4*)&kl_g[go];
            *(uint4*)&Vh[row*SR+c8] = *(const uint4*)&g_vth[gv];
            *(uint4*)&Vl[row*SR+c8] = *(const uint4*)&g_vtl[gv];
        }
        __syncthreads();

        float c[8][4] = {};
        #pragma unroll
        for (int ks = 0; ks < 4; ++ks) {
            #pragma unroll
            for (int np = 0; np < 4; ++np) {
                unsigned boff = (unsigned)(((np*16 + browin)*SR + ks*16 + bcol) * 2);
                u32 bH[4], bL[4];
                ldsm4(bH[0],bH[1],bH[2],bH[3], kh_b + boff);
                ldsm4(bL[0],bL[1],bL[2],bL[3], kl_b + boff);
                mma_bf16(c[2*np],   qH[ks], bH[0], bH[1]);
                mma_bf16(c[2*np],   qH[ks], bL[0], bL[1]);
                mma_bf16(c[2*np],   qL[ks], bH[0], bH[1]);
                mma_bf16(c[2*np+1], qH[ks], bH[2], bH[3]);
                mma_bf16(c[2*np+1], qH[ks], bL[2], bL[3]);
                mma_bf16(c[2*np+1], qL[ks], bH[2], bH[3]);
            }
        }

        #pragma unroll
        for (int hf = 0; hf < 2; ++hf) {
            float mx = -1e30f;
            #pragma unroll
            for (int nf = 0; nf < 8; ++nf)
                mx = fmaxf(mx, fmaxf(c[nf][2*hf], c[nf][2*hf+1]));
            mx = fmaxf(mx, __shfl_xor_sync(0xffffffffu, mx, 1));
            mx = fmaxf(mx, __shfl_xor_sync(0xffffffffu, mx, 2));
            float mn   = fmaxf(m[hf], mx);
            float corr = ex2(m[hf] - mn);
            float rs = 0.f;
            #pragma unroll
            for (int nf = 0; nf < 8; ++nf) {
                float p0 = ex2(c[nf][2*hf]   - mn);
                float p1 = ex2(c[nf][2*hf+1] - mn);
                c[nf][2*hf] = p0; c[nf][2*hf+1] = p1;
                rs += p0 + p1;
            }
            rs += __shfl_xor_sync(0xffffffffu, rs, 1);
            rs += __shfl_xor_sync(0xffffffffu, rs, 2);
            l[hf] = l[hf]*corr + rs;
            m[hf] = mn;
            #pragma unroll
            for (int nf = 0; nf < 8; ++nf) {
                o[nf][2*hf]   *= corr;
                o[nf][2*hf+1] *= corr;
            }
        }

        #pragma unroll
        for (int ks = 0; ks < 4; ++ks) {
            u32 pH[4], pL[4];
            split2(c[2*ks][0],   c[2*ks][1],   pH[0], pL[0]);
            split2(c[2*ks][2],   c[2*ks][3],   pH[1], pL[1]);
            split2(c[2*ks+1][0], c[2*ks+1][1], pH[2], pL[2]);
            split2(c[2*ks+1][2], c[2*ks+1][3], pH[3], pL[3]);
            #pragma unroll
            for (int np = 0; np < 4; ++np) {
                unsigned boff = (unsigned)(((np*16 + browin)*SR + ks*16 + bcol) * 2);
                u32 bH[4], bL[4];
                ldsm4(bH[0],bH[1],bH[2],bH[3], vh_b + boff);
                ldsm4(bL[0],bL[1],bL[2],bL[3], vl_b + boff);
                mma_bf16(o[2*np],   pH, bH[0], bH[1]);
                mma_bf16(o[2*np],   pH, bL[0], bL[1]);
                mma_bf16(o[2*np],   pL, bH[0], bH[1]);
                mma_bf16(o[2*np+1], pH, bH[2], bH[3]);
                mma_bf16(o[2*np+1], pH, bL[2], bL[3]);
                mma_bf16(o[2*np+1], pL, bH[2], bH[3]);
            }
        }
        __syncthreads();
    }

    const int gid = lane >> 2, tig = lane & 3;
    const float inv[2] = {1.f/l[0], 1.f/l[1]};
    #pragma unroll
    for (int hf = 0; hf < 2; ++hf)
        #pragma unroll
        for (int nf = 0; nf < 8; ++nf) {
            int r = q0 + warp*16 + gid + hf*8;
            int col = h*64 + nf*8 + tig*2;
            float2 y;
            y.x = o[nf][2*hf]  *inv[hf];
            y.y = o[nf][2*hf+1]*inv[hf];
            *(float2*)&og[(size_t)(b*SS + r)*DD + col] = y;
        }
}

// ============================================================
// Kernel 3a (FUSED): combine streams + GroupNorm stats partials
// ============================================================
__global__ __launch_bounds__(256) void combine_stats_kernel(
    const float* __restrict__ lq1, const float* __restrict__ lk1,
    const float* __restrict__ lq2, const float* __restrict__ lk2)
{
    const int gi = blockIdx.y;
    const int b = gi >> 2, g = gi & 3;
    const int r0 = blockIdx.x * 64;
    const int tid = threadIdx.x;

    const int h0 = g*2;
    float lam0 = __expf(lq1[h0]*lk1[h0])     - __expf(lq2[h0]*lk2[h0])     + 0.2f;
    float lam1 = __expf(lq1[h0+1]*lk1[h0+1]) - __expf(lq2[h0+1]*lk2[h0+1]) + 0.2f;

    const size_t base = (size_t)b*SS*DD + g*128;

    float s = 0.f, ss = 0.f;
    #pragma unroll
    for (int it = 0; it < 8; ++it) {
        int idx = tid + it*256;
        int r = idx >> 5, c4 = (idx & 31) << 2;
        float lam = (c4 & 64) ? lam1 : lam0;
        size_t e = base + (size_t)(r0 + r)*DD + c4;
        float4 a = *(const float4*)&g_o1[e];
        float4 c = *(const float4*)&g_o2[e];
        float4 o;
        o.x = a.x - lam*c.x; o.y = a.y - lam*c.y;
        o.z = a.z - lam*c.z; o.w = a.w - lam*c.w;
        *(float4*)&g_o[e] = o;
        s  += o.x + o.y + o.z + o.w;
        ss += o.x*o.x + o.y*o.y + o.z*o.z + o.w*o.w;
    }
    __shared__ float rs[256], rq[256];
    rs[tid] = s; rq[tid] = ss;
    __syncthreads();
    for (int off = 128; off > 0; off >>= 1) {
        if (tid < off) { rs[tid] += rs[tid+off]; rq[tid] += rq[tid+off]; }
        __syncthreads();
    }
    if (tid == 0) {
        g_part_s[gi*32 + blockIdx.x] = rs[0];
        g_part_q[gi*32 + blockIdx.x] = rq[0];
    }
}

// ============================================================
// Kernel 3b: stats stage 2
// ============================================================
__global__ __launch_bounds__(32) void gn_stats2_kernel()
{
    int gi = threadIdx.x;
    if (gi >= BB*GG) return;
    float s = 0.f, q = 0.f;
    #pragma unroll
    for (int i = 0; i < 32; ++i) {
        s += g_part_s[gi*32 + i];
        q += g_part_q[gi*32 + i];
    }
    const float n = (float)(SS*128);
    float mu  = s / n;
    float var = q / n - mu*mu;
    g_mu[gi]   = mu;
    g_rstd[gi] = rsqrtf(var + 1e-5f);
}

// ============================================================
// Kernel 4: output GEMM with GroupNorm apply+split fused in A-load
// ============================================================
__global__ __launch_bounds__(128) void out_mma_kernel(
    const float* __restrict__ gw, const float* __restrict__ gb,
    const float* __restrict__ bias, float* __restrict__ y)
{
    __shared__ __nv_bfloat16 Ah[64*SR], Al[64*SR], Bh[64*SR], Bl[64*SR];

    const int tid = threadIdx.x, lane = tid & 31, warp = tid >> 5;
    const int m0 = blockIdx.x * 64, n0 = blockIdx.y * 64;
    const int bidx = m0 >> 11;

    const __nv_bfloat16* Wh = g_wh + (size_t)5*DD*DD;
    const __nv_bfloat16* Wl = g_wl + (size_t)5*DD*DD;

    float c[8][4] = {};

    const unsigned ah_b = smem_u32(Ah), al_b = smem_u32(Al);
    const unsigned bh_b = smem_u32(Bh), bl_b = smem_u32(Bl);
    const int arow   = warp*16 + (lane & 7) + ((lane >> 3) & 1) * 8;
    const int acol   = ((lane >> 4) << 3);
    const int browin = (lane & 7) + ((lane >> 4) << 3);
    const int bcol   = (((lane >> 3) & 1) << 3);

    for (int k0 = 0; k0 < DD; k0 += 64) {
        #pragma unroll
        for (int it = 0; it < 4; ++it) {
            int idx = tid + it*128;
            int row = idx >> 3, c8 = (idx & 7) << 3;
            int col = k0 + c8;
            int gi = bidx*4 + (col >> 7);
            float mu = g_mu[gi], rst = g_rstd[gi];
            size_t ga = (size_t)(m0+row)*DD + col;
            float4 a0 = *(const float4*)&g_o[ga];
            float4 a1 = *(const float4*)&g_o[ga+4];
            float4 w0 = *(const float4*)&gw[col];
            float4 w1 = *(const float4*)&gw[col+4];
            float4 s0 = *(const float4*)&gb[col];
            float4 s1 = *(const float4*)&gb[col+4];
            float v0 = (a0.x - mu)*rst*w0.x + s0.x;
            float v1 = (a0.y - mu)*rst*w0.y + s0.y;
            float v2 = (a0.z - mu)*rst*w0.z + s0.z;
            float v3 = (a0.w - mu)*rst*w0.w + s0.w;
            float v4 = (a1.x - mu)*rst*w1.x + s1.x;
            float v5 = (a1.y - mu)*rst*w1.y + s1.y;
            float v6 = (a1.z - mu)*rst*w1.z + s1.z;
            float v7 = (a1.w - mu)*rst*w1.w + s1.w;
            uint4 hv, lv;
            split2(v0, v1, hv.x, lv.x);
            split2(v2, v3, hv.y, lv.y);
            split2(v4, v5, hv.z, lv.z);
            split2(v6, v7, hv.w, lv.w);
            *(uint4*)&Ah[row*SR+c8] = hv;
            *(uint4*)&Al[row*SR+c8] = lv;
            size_t gbo = (size_t)(n0+row)*DD + k0 + c8;
            *(uint4*)&Bh[row*SR+c8] = *(const uint4*)&Wh[gbo];
            *(uint4*)&Bl[row*SR+c8] = *(const uint4*)&Wl[gbo];
        }
        __syncthreads();
        mma_tile64(c, ah_b, al_b, bh_b, bl_b, arow, acol, browin, bcol);
        __syncthreads();
    }

    const int gid = lane >> 2, tig = lane & 3;
    #pragma unroll
    for (int nf = 0; nf < 8; ++nf)
        #pragma unroll
        for (int hf = 0; hf < 2; ++hf) {
            int r = m0 + warp*16 + gid + hf*8;
            int n = n0 + nf*8 + tig*2;
            float2 o;
            o.x = c[nf][2*hf]   + bias[n];
            o.y = c[nf][2*hf+1] + bias[n+1];
            *(float2*)&y[(size_t)r*DD + n] = o;
        }
}

// ============================================================
// launch
// ============================================================
extern "C" void kernel_launch(void* const* d_in, const int* in_sizes, int n_in,
                              void* d_out, int out_size)
{
    const float* x   = (const float*)d_in[0];
    const float* K1w = (const float*)d_in[1];
    const float* K1b = (const float*)d_in[2];
    const float* Q1w = (const float*)d_in[3];
    const float* K2w = (const float*)d_in[4];
    const float* K2b = (const float*)d_in[5];
    const float* Q2w = (const float*)d_in[6];
    const float* Vw  = (const float*)d_in[7];
    const float* lq1 = (const float*)d_in[8];
    const float* lk1 = (const float*)d_in[9];
    const float* lq2 = (const float*)d_in[10];
    const float* lk2 = (const float*)d_in[11];
    const float* gw  = (const float*)d_in[12];
    const float* gb  = (const float*)d_in[13];
    const float* Ow  = (const float*)d_in[14];
    const float* Ob  = (const float*)d_in[15];
    float* y = (float*)d_out;

    const int NSPLIT = (NROW*DD/4 + 6*DD*DD/4 + 255) / 256;
    split_inputs_kernel<<<NSPLIT, 256>>>(x, Q1w, K1w, Q2w, K2w, Vw, Ow);
    qkv_mma_kernel<<<dim3(NROW/64, DD/64, 5), 128>>>(K1b, K2b);
    attn_mma_kernel<<<dim3(SS/64, BB*HH, 2), 128>>>();
    combine_stats_kernel<<<dim3(32, BB*GG), 256>>>(lq1, lk1, lq2, lk2);
    gn_stats2_kernel<<<1, 32>>>();
    out_mma_kernel<<<dim3(NROW/64, DD/64), 128>>>(gw, gb, Ob, y);
}